// round 15
// baseline (speedup 1.0000x reference)
#include <cuda_runtime.h>
#include <cuda_bf16.h>
#include <math.h>
#include <stdint.h>

#define NS 100000
#define NI 20000
#define D  128
#define L  2
#define E1 600000
#define E2 500000

// ---------------- scratch (static device globals: allocation-free) ----------------
__device__ float g_xs  [(size_t)NS * D];
__device__ float g_item [(size_t)NI * D];   // layer-1 pre-BN item output
__device__ float g_item2[(size_t)NI * D];   // layer-2 pre-BN item output
__device__ float g_bn[2 * D];               // statically zero; bn_final re-zeroes after use
__device__ float g_sc1[D];
__device__ float g_sh1[D];
__device__ float g_sc2[D];
__device__ float g_sh2[D];
// packed weights: 10 matrices (2 layers x 5): hi image (16384 bf16) + lo image (16384 bf16)
__device__ __nv_bfloat16 g_wpack[10 * 32768];
// CSR structures (private scratch per edge list so builds can run concurrently)
__device__ int g_deg_a[NI + 2];
__device__ int g_deg_b[NS + 2];
__device__ int g_deg_c[NS + 2];
__device__ int g_bsum_a[128];
__device__ int g_bsum_b[128];
__device__ int g_bsum_c[128];
__device__ int g_rp_resp[NI + 1];
__device__ int g_rp_rev[NS + 1];
__device__ int g_rp_prec[NS + 1];
__device__ int g_col_resp[E1];
__device__ int g_col_rev[E1];
__device__ int g_col_prec[E2];

// ---------------- smem swizzle: 128 rows x 256B, 16B chunks XOR'd by row ----------------
__device__ __forceinline__ uint32_t sw_off(int row, int k) {
    return (uint32_t)(row * 256 + (((k >> 3) ^ (row & 7)) << 4) + ((k & 7) << 1));
}

__device__ __forceinline__ uint32_t s2u(const void* p) {
    uint32_t a;
    asm("{ .reg .u64 t; cvta.to.shared.u64 t, %1; cvt.u32.u64 %0, t; }" : "=r"(a) : "l"(p));
    return a;
}

__device__ __forceinline__ void ldsm4(uint32_t& r0, uint32_t& r1, uint32_t& r2, uint32_t& r3,
                                      uint32_t addr) {
    asm volatile("ldmatrix.sync.aligned.m8n8.x4.shared.b16 {%0,%1,%2,%3}, [%4];"
                 : "=r"(r0), "=r"(r1), "=r"(r2), "=r"(r3) : "r"(addr));
}

__device__ __forceinline__ void mma16816(float* c, uint32_t a0, uint32_t a1, uint32_t a2,
                                         uint32_t a3, uint32_t b0, uint32_t b1) {
    asm volatile("mma.sync.aligned.m16n8k16.row.col.f32.bf16.bf16.f32 "
                 "{%0,%1,%2,%3}, {%4,%5,%6,%7}, {%8,%9}, {%0,%1,%2,%3};"
                 : "+f"(c[0]), "+f"(c[1]), "+f"(c[2]), "+f"(c[3])
                 : "r"(a0), "r"(a1), "r"(a2), "r"(a3), "r"(b0), "r"(b1));
}

__device__ __forceinline__ void cpasync16(uint32_t s, const void* g) {
    asm volatile("cp.async.cg.shared.global [%0], [%1], 16;" :: "r"(s), "l"(g));
}

// ================= utility kernels =================
__global__ void zero_int(int* __restrict__ p, int n) {
    int i = blockIdx.x * blockDim.x + threadIdx.x;
    if (i < n) p[i] = 0;
}

// ================= CSR build (three-stage multi-block scan) =================
__global__ void hist_kernel(const int* __restrict__ dst, int E, int* __restrict__ deg) {
    int e = blockIdx.x * blockDim.x + threadIdx.x;
    if (e < E) atomicAdd(&deg[dst[e]], 1);
}

__global__ void scan_sum(const int* __restrict__ deg, int* __restrict__ bsum, int M) {
    __shared__ int wsum[8];
    int t = threadIdx.x;
    int base = blockIdx.x * 1024 + t * 4;
    int s = 0;
#pragma unroll
    for (int j = 0; j < 4; ++j) s += (base + j < M) ? deg[base + j] : 0;
#pragma unroll
    for (int o = 16; o > 0; o >>= 1) s += __shfl_down_sync(0xFFFFFFFFu, s, o);
    if ((t & 31) == 0) wsum[t >> 5] = s;
    __syncthreads();
    if (t == 0) {
        int r = 0;
#pragma unroll
        for (int w = 0; w < 8; ++w) r += wsum[w];
        bsum[blockIdx.x] = r;
    }
}

__global__ void scan_offsets(int* __restrict__ bsum, int nb) {
    if (threadIdx.x == 0 && blockIdx.x == 0) {
        int r = 0;
        for (int b = 0; b < nb; ++b) { int x = bsum[b]; bsum[b] = r; r += x; }
    }
}

__global__ void scan_block(const int* __restrict__ deg, const int* __restrict__ bsum,
                           int* __restrict__ rp, int M) {
    __shared__ int wsum[8];
    int t = threadIdx.x, lane = t & 31, wid = t >> 5;
    int base = blockIdx.x * 1024 + t * 4;
    int v[4];
#pragma unroll
    for (int j = 0; j < 4; ++j) v[j] = (base + j < M) ? deg[base + j] : 0;
    int tsum = v[0] + v[1] + v[2] + v[3];
    int incl = tsum;
#pragma unroll
    for (int o = 1; o < 32; o <<= 1) {
        int n = __shfl_up_sync(0xFFFFFFFFu, incl, o);
        if (lane >= o) incl += n;
    }
    if (lane == 31) wsum[wid] = incl;
    __syncthreads();
    if (t == 0) {
        int r = 0;
#pragma unroll
        for (int w = 0; w < 8; ++w) { int x = wsum[w]; wsum[w] = r; r += x; }
    }
    __syncthreads();
    int run = incl - tsum + wsum[wid] + bsum[blockIdx.x];
#pragma unroll
    for (int j = 0; j < 4; ++j) {
        if (base + j < M) { rp[base + j] = run; run += v[j]; }
    }
}

__global__ void fill_kernel(const int* __restrict__ src, const int* __restrict__ dst, int E,
                            const int* __restrict__ rp, int* __restrict__ fillc,
                            int* __restrict__ col) {
    int e = blockIdx.x * blockDim.x + threadIdx.x;
    if (e >= E) return;
    int d = dst[e];
    int pos = rp[d] + atomicAdd(&fillc[d], 1);
    col[pos] = src[e];
}

// Pack all 10 weight matrices into bf16 hi/lo swizzled images ([n][k] rows of 256B).
__global__ void pack_w(const float* __restrict__ Wl_ri, const float* __restrict__ Wr_ri,
                       const float* __restrict__ Wl_rs, const float* __restrict__ Wr_rs,
                       const float* __restrict__ W_p, __nv_bfloat16* __restrict__ dst) {
    int gid = blockIdx.x * blockDim.x + threadIdx.x;
    if (gid >= 10 * 16384) return;
    int mid = gid >> 14;
    int idx = gid & 16383;
    int l = mid / 5, which = mid % 5;
    const float* src;
    switch (which) {
        case 0: src = Wl_ri; break;
        case 1: src = Wr_ri; break;
        case 2: src = Wl_rs; break;
        case 3: src = Wr_rs; break;
        default: src = W_p; break;
    }
    float a = src[(size_t)l * 16384 + idx];
    int n = idx >> 7, k = idx & 127;
    __nv_bfloat16 hi = __float2bfloat16(a);
    __nv_bfloat16 lo = __float2bfloat16(a - __bfloat162float(hi));
    uint32_t off = sw_off(n, k) >> 1;
    dst[(size_t)mid * 32768 + off] = hi;
    dst[(size_t)mid * 32768 + 16384 + off] = lo;
}

// ====== pipelined HMMA fused GEMM with in-line CSR gather A-operands ======
// Out = f( sum_p Ap@Wp^T + b1 [+ b2] ), bf16 3-term split per pass.
// Each pass: dense (rp==null) or CSR gather over X rows:
//   gmode 0: mean; 1: sum; 2: deg>0 ? mean*sc+sh : 0
// Dense pass == aff_pass applies per-column affine (sc,sh) at convert time.
#define A_HI 0
#define A_LO 32768
#define W_BUF0 65536
#define W_BUF1 131072
#define BN_OFF 196608
#define SMEM_TC (196608 + 1024 + 16)

__device__ __forceinline__ void load_pass(const float* __restrict__ X,
                                          const int* __restrict__ rp,
                                          const int* __restrict__ col, int gmode,
                                          const float* __restrict__ sc,
                                          const float* __restrict__ sh,
                                          int m0, int M, int tid, float4 (&pa)[4][2]) {
#pragma unroll
    for (int it = 0; it < 4; ++it) {
        int idx = tid + it * 512;
        int row = idx >> 4;
        int k0 = (idx & 15) << 3;
        int m = m0 + row;
        float4 a0 = make_float4(0.f, 0.f, 0.f, 0.f), a1 = a0;
        if (m < M) {
            if (rp == nullptr) {
                const float* ap = X + (size_t)m * D + k0;
                a0 = __ldg((const float4*)ap);
                a1 = __ldg((const float4*)(ap + 4));
            } else {
                int beg = __ldg(rp + m), end = __ldg(rp + m + 1);
                int i = beg;
                for (; i + 2 <= end; i += 2) {
                    int s0 = __ldg(col + i);
                    int s1 = __ldg(col + i + 1);
                    const float* x0 = X + (size_t)s0 * D + k0;
                    const float* x1 = X + (size_t)s1 * D + k0;
                    float4 v00 = __ldg((const float4*)x0);
                    float4 v01 = __ldg((const float4*)(x0 + 4));
                    float4 v10 = __ldg((const float4*)x1);
                    float4 v11 = __ldg((const float4*)(x1 + 4));
                    a0.x += v00.x + v10.x; a0.y += v00.y + v10.y;
                    a0.z += v00.z + v10.z; a0.w += v00.w + v10.w;
                    a1.x += v01.x + v11.x; a1.y += v01.y + v11.y;
                    a1.z += v01.z + v11.z; a1.w += v01.w + v11.w;
                }
                if (i < end) {
                    int s = __ldg(col + i);
                    const float* xp = X + (size_t)s * D + k0;
                    float4 v0 = __ldg((const float4*)xp);
                    float4 v1 = __ldg((const float4*)(xp + 4));
                    a0.x += v0.x; a0.y += v0.y; a0.z += v0.z; a0.w += v0.w;
                    a1.x += v1.x; a1.y += v1.y; a1.z += v1.z; a1.w += v1.w;
                }
                if (gmode != 1) {
                    float mm = 1.f / fmaxf((float)(end - beg), 1.f);
                    a0.x *= mm; a0.y *= mm; a0.z *= mm; a0.w *= mm;
                    a1.x *= mm; a1.y *= mm; a1.z *= mm; a1.w *= mm;
                    if (gmode == 2 && end > beg) {
                        float4 s0 = __ldg((const float4*)(sc + k0));
                        float4 s1 = __ldg((const float4*)(sc + k0 + 4));
                        float4 h0 = __ldg((const float4*)(sh + k0));
                        float4 h1 = __ldg((const float4*)(sh + k0 + 4));
                        a0.x = a0.x * s0.x + h0.x; a0.y = a0.y * s0.y + h0.y;
                        a0.z = a0.z * s0.z + h0.z; a0.w = a0.w * s0.w + h0.w;
                        a1.x = a1.x * s1.x + h1.x; a1.y = a1.y * s1.y + h1.y;
                        a1.z = a1.z * s1.z + h1.z; a1.w = a1.w * s1.w + h1.w;
                    }
                }
            }
        }
        pa[it][0] = a0; pa[it][1] = a1;
    }
}

__global__ __launch_bounds__(512, 1)
void gemm_tc(const float* __restrict__ A1, const int* __restrict__ rp1,
             const int* __restrict__ col1, int g1,
             const float* __restrict__ A2, const int* __restrict__ rp2,
             const int* __restrict__ col2, int g2,
             const float* __restrict__ A3, const int* __restrict__ rp3,
             const int* __restrict__ col3, int g3,
             const __nv_bfloat16* __restrict__ W1p, const __nv_bfloat16* __restrict__ W2p,
             const __nv_bfloat16* __restrict__ W3p,
             const float* __restrict__ sc, const float* __restrict__ sh, int aff_pass,
             const float* __restrict__ bias1, const float* __restrict__ bias2,
             float out_scale, int do_elu, float* __restrict__ bn,
             float* __restrict__ Out, int M) {
    extern __shared__ char smem[];
    const uint32_t sb = s2u(smem);
    float* bnS = (float*)(smem + BN_OFF);

    const int tid = threadIdx.x;
    const int w = tid >> 5, lane = tid & 31;
    const int wm = w >> 2, wn = w & 3;          // 4 x 4 warp grid
    const int m_base = wm * 32, n_base = wn * 32;
    const int m0 = blockIdx.x * 128;
    const int qr = lane >> 2, qc = lane & 3;

    if (tid < 256) bnS[tid] = 0.f;

    float acc[2][4][4];
#pragma unroll
    for (int a = 0; a < 2; ++a)
#pragma unroll
        for (int b = 0; b < 4; ++b)
#pragma unroll
            for (int c = 0; c < 4; ++c) acc[a][b][c] = 0.f;

    const float* As[3] = {A1, A2, A3};
    const int* rps[3] = {rp1, rp2, rp3};
    const int* cols[3] = {col1, col2, col3};
    const int gms[3] = {g1, g2, g3};
    const __nv_bfloat16* Wsp[3] = {W1p, W2p, W3p};
    const int P = (A3 != nullptr) ? 3 : ((A2 != nullptr) ? 2 : 1);

    {
        const char* wg = (const char*)Wsp[0];
#pragma unroll
        for (int it = 0; it < 8; ++it) {
            int i = tid + it * 512;
            cpasync16(sb + W_BUF0 + i * 16, wg + (size_t)i * 16);
        }
        asm volatile("cp.async.commit_group;" ::: "memory");
    }
    float4 pa[4][2];
    load_pass(As[0], rps[0], cols[0], gms[0], sc, sh, m0, M, tid, pa);

    for (int p = 0; p < P; ++p) {
        asm volatile("cp.async.wait_group 0;" ::: "memory");

#pragma unroll
        for (int it = 0; it < 4; ++it) {
            int idx = tid + it * 512;
            int row = idx >> 4;
            int k0 = (idx & 15) << 3;
            float av[8] = {pa[it][0].x, pa[it][0].y, pa[it][0].z, pa[it][0].w,
                           pa[it][1].x, pa[it][1].y, pa[it][1].z, pa[it][1].w};
            if (p == aff_pass) {
                float4 s0 = __ldg((const float4*)(sc + k0));
                float4 s1 = __ldg((const float4*)(sc + k0 + 4));
                float4 h0 = __ldg((const float4*)(sh + k0));
                float4 h1 = __ldg((const float4*)(sh + k0 + 4));
                av[0] = av[0] * s0.x + h0.x; av[1] = av[1] * s0.y + h0.y;
                av[2] = av[2] * s0.z + h0.z; av[3] = av[3] * s0.w + h0.w;
                av[4] = av[4] * s1.x + h1.x; av[5] = av[5] * s1.y + h1.y;
                av[6] = av[6] * s1.z + h1.z; av[7] = av[7] * s1.w + h1.w;
            }
            __nv_bfloat16 hv[8], lv[8];
#pragma unroll
            for (int j = 0; j < 8; ++j) {
                hv[j] = __float2bfloat16(av[j]);
                lv[j] = __float2bfloat16(av[j] - __bfloat162float(hv[j]));
            }
            uint32_t off = sw_off(row, k0);
            *(uint4*)(smem + A_HI + off) = *(uint4*)hv;
            *(uint4*)(smem + A_LO + off) = *(uint4*)lv;
        }
        __syncthreads();

        if (p + 1 < P) {
            const char* wg = (const char*)Wsp[p + 1];
            uint32_t wb = sb + (((p + 1) & 1) ? W_BUF1 : W_BUF0);
#pragma unroll
            for (int it = 0; it < 8; ++it) {
                int i = tid + it * 512;
                cpasync16(wb + i * 16, wg + (size_t)i * 16);
            }
            asm volatile("cp.async.commit_group;" ::: "memory");
            load_pass(As[p + 1], rps[p + 1], cols[p + 1], gms[p + 1], sc, sh, m0, M, tid, pa);
        }

        const uint32_t wbase = sb + ((p & 1) ? W_BUF1 : W_BUF0);
        for (int ks = 0; ks < 8; ++ks) {
            const int kc = ks * 16;
            uint32_t ah[2][4], al[2][4], bh[2][4], bl[2][4];
#pragma unroll
            for (int mt = 0; mt < 2; ++mt) {
                int row = m_base + mt * 16 + (lane & 15);
                int kk = kc + ((lane >> 4) << 3);
                uint32_t off = sw_off(row, kk);
                ldsm4(ah[mt][0], ah[mt][1], ah[mt][2], ah[mt][3], sb + A_HI + off);
                ldsm4(al[mt][0], al[mt][1], al[mt][2], al[mt][3], sb + A_LO + off);
            }
#pragma unroll
            for (int ng = 0; ng < 2; ++ng) {
                int n = n_base + ng * 16 + (lane & 7) + ((lane >> 4) << 3);
                int kk = kc + (((lane >> 3) & 1) << 3);
                uint32_t off = sw_off(n, kk);
                ldsm4(bh[ng][0], bh[ng][1], bh[ng][2], bh[ng][3], wbase + off);
                ldsm4(bl[ng][0], bl[ng][1], bl[ng][2], bl[ng][3], wbase + 32768 + off);
            }
#pragma unroll
            for (int mt = 0; mt < 2; ++mt)
#pragma unroll
                for (int ng = 0; ng < 2; ++ng) {
                    mma16816(acc[mt][ng * 2 + 0], ah[mt][0], ah[mt][1], ah[mt][2], ah[mt][3],
                             bh[ng][0], bh[ng][1]);
                    mma16816(acc[mt][ng * 2 + 1], ah[mt][0], ah[mt][1], ah[mt][2], ah[mt][3],
                             bh[ng][2], bh[ng][3]);
                    mma16816(acc[mt][ng * 2 + 0], ah[mt][0], ah[mt][1], ah[mt][2], ah[mt][3],
                             bl[ng][0], bl[ng][1]);
                    mma16816(acc[mt][ng * 2 + 1], ah[mt][0], ah[mt][1], ah[mt][2], ah[mt][3],
                             bl[ng][2], bl[ng][3]);
                    mma16816(acc[mt][ng * 2 + 0], al[mt][0], al[mt][1], al[mt][2], al[mt][3],
                             bh[ng][0], bh[ng][1]);
                    mma16816(acc[mt][ng * 2 + 1], al[mt][0], al[mt][1], al[mt][2], al[mt][3],
                             bh[ng][2], bh[ng][3]);
                }
        }
        __syncthreads();
    }

    // ---------------- epilogue ----------------
    float bcol[8];
#pragma unroll
    for (int nt = 0; nt < 4; ++nt)
#pragma unroll
        for (int par = 0; par < 2; ++par) {
            int c = n_base + nt * 8 + qc * 2 + par;
            float bb = 0.f;
            if (bias1 != nullptr) bb += bias1[c];
            if (bias2 != nullptr) bb += bias2[c];
            bcol[nt * 2 + par] = bb;
        }

    float cs[8], cq[8];
#pragma unroll
    for (int j = 0; j < 8; ++j) { cs[j] = 0.f; cq[j] = 0.f; }

#pragma unroll
    for (int mt = 0; mt < 2; ++mt)
#pragma unroll
        for (int jh = 0; jh < 2; ++jh) {
            int m = m0 + m_base + mt * 16 + qr + jh * 8;
            bool valid = (m < M);
            float2 vals[4];
#pragma unroll
            for (int nt = 0; nt < 4; ++nt) {
                float v0 = acc[mt][nt][jh * 2 + 0] + bcol[nt * 2 + 0];
                float v1 = acc[mt][nt][jh * 2 + 1] + bcol[nt * 2 + 1];
                if (do_elu) {
                    v0 = (v0 > 0.f) ? v0 : expm1f(v0);
                    v1 = (v1 > 0.f) ? v1 : expm1f(v1);
                }
                v0 *= out_scale; v1 *= out_scale;
                vals[nt] = make_float2(v0, v1);
                if (valid) {
                    cs[nt * 2 + 0] += v0; cq[nt * 2 + 0] += v0 * v0;
                    cs[nt * 2 + 1] += v1; cq[nt * 2 + 1] += v1 * v1;
                }
            }
            if (valid) {
                float* op = Out + (size_t)m * D + n_base + qc * 2;
#pragma unroll
                for (int nt = 0; nt < 4; ++nt)
                    *(float2*)(op + nt * 8) = vals[nt];
            }
        }

    if (bn != nullptr) {
#pragma unroll
        for (int j = 0; j < 8; ++j) {
#pragma unroll
            for (int o = 16; o >= 4; o >>= 1) {
                cs[j] += __shfl_down_sync(0xFFFFFFFFu, cs[j], o);
                cq[j] += __shfl_down_sync(0xFFFFFFFFu, cq[j], o);
            }
        }
        if (lane < 4) {
#pragma unroll
            for (int nt = 0; nt < 4; ++nt)
#pragma unroll
                for (int par = 0; par < 2; ++par) {
                    int c = n_base + nt * 8 + lane * 2 + par;
                    atomicAdd(&bnS[c], cs[nt * 2 + par]);
                    atomicAdd(&bnS[128 + c], cq[nt * 2 + par]);
                }
        }
        __syncthreads();
        if (tid < 256) atomicAdd(&bn[tid], bnS[tid]);
    }
}

// ================= batchnorm =================
__global__ void bn_final(float* __restrict__ bn, const float* __restrict__ g,
                         const float* __restrict__ b, float* __restrict__ scale,
                         float* __restrict__ shift, float invN) {
    int c = threadIdx.x;
    float m = bn[c] * invN;
    float var = bn[D + c] * invN - m * m;
    float rs = rsqrtf(var + 1e-5f);
    float sc = g[c] * rs;
    scale[c] = sc;
    shift[c] = b[c] - m * sc;
    bn[c] = 0.f;
    bn[D + c] = 0.f;
}

__global__ void bn_apply(const float4* __restrict__ x, const float* __restrict__ scale,
                         const float* __restrict__ shift, float4* __restrict__ y, int n4) {
    int i = blockIdx.x * blockDim.x + threadIdx.x;
    if (i >= n4) return;
    int c = (i & 31) * 4;
    float4 v = x[i];
    v.x = v.x * scale[c + 0] + shift[c + 0];
    v.y = v.y * scale[c + 1] + shift[c + 1];
    v.z = v.z * scale[c + 2] + shift[c + 2];
    v.w = v.w * scale[c + 3] + shift[c + 3];
    y[i] = v;
}

// ================= host =================
static inline void build_csr(const int* src, const int* dst, int E, int N,
                             int* deg, int* bsum, int* rp, int* col, cudaStream_t st) {
    int M = N + 1;
    int nb = (M + 1023) / 1024;
    zero_int<<<(M + 255) / 256, 256, 0, st>>>(deg, M);
    hist_kernel<<<(E + 255) / 256, 256, 0, st>>>(dst, E, deg);
    scan_sum<<<nb, 256, 0, st>>>(deg, bsum, M);
    scan_offsets<<<1, 32, 0, st>>>(bsum, nb);
    scan_block<<<nb, 256, 0, st>>>(deg, bsum, rp, M);
    zero_int<<<(N + 255) / 256, 256, 0, st>>>(deg, N);
    fill_kernel<<<(E + 255) / 256, 256, 0, st>>>(src, dst, E, rp, deg, col);
}

extern "C" void kernel_launch(void* const* d_in, const int* in_sizes, int n_in,
                              void* d_out, int out_size) {
    const float* x_student = (const float*)d_in[0];
    const float* x_item    = (const float*)d_in[1];
    const float* Wl_ri = (const float*)d_in[2];
    const float* bl_ri = (const float*)d_in[3];
    const float* Wr_ri = (const float*)d_in[4];
    const float* Wl_rs = (const float*)d_in[5];
    const float* bl_rs = (const float*)d_in[6];
    const float* Wr_rs = (const float*)d_in[7];
    const float* W_p   = (const float*)d_in[8];
    const float* b_p   = (const float*)d_in[9];
    const float* bn_g  = (const float*)d_in[10];
    const float* bn_b  = (const float*)d_in[11];
    const int* resp_src = (const int*)d_in[12];
    const int* resp_dst = (const int*)d_in[13];
    const int* rev_src  = (const int*)d_in[14];
    const int* rev_dst  = (const int*)d_in[15];
    const int* prec_src = (const int*)d_in[16];
    const int* prec_dst = (const int*)d_in[17];
    float* out = (float*)d_out;

    static int configured = 0;
    static cudaStream_t s1, s2, s3;
    static cudaEvent_t evRoot, evPack, evB2, evB3, evXs1, evXi1, evDone;
    if (!configured) {
        cudaFuncSetAttribute(gemm_tc, cudaFuncAttributeMaxDynamicSharedMemorySize, SMEM_TC);
        cudaStreamCreateWithFlags(&s1, cudaStreamNonBlocking);
        cudaStreamCreateWithFlags(&s2, cudaStreamNonBlocking);
        cudaStreamCreateWithFlags(&s3, cudaStreamNonBlocking);
        cudaEventCreateWithFlags(&evRoot, cudaEventDisableTiming);
        cudaEventCreateWithFlags(&evPack, cudaEventDisableTiming);
        cudaEventCreateWithFlags(&evB2, cudaEventDisableTiming);
        cudaEventCreateWithFlags(&evB3, cudaEventDisableTiming);
        cudaEventCreateWithFlags(&evXs1, cudaEventDisableTiming);
        cudaEventCreateWithFlags(&evXi1, cudaEventDisableTiming);
        cudaEventCreateWithFlags(&evDone, cudaEventDisableTiming);
        configured = 1;
    }

    float *xs, *item, *item2, *bn;
    float *sc1, *sh1, *sc2, *sh2;
    __nv_bfloat16* wpack;
    int *deg_a, *deg_b, *deg_c, *bsum_a, *bsum_b, *bsum_c;
    int *rp_resp, *rp_rev, *rp_prec, *col_resp, *col_rev, *col_prec;
    cudaGetSymbolAddress((void**)&xs,      g_xs);
    cudaGetSymbolAddress((void**)&item,    g_item);
    cudaGetSymbolAddress((void**)&item2,   g_item2);
    cudaGetSymbolAddress((void**)&bn,      g_bn);
    cudaGetSymbolAddress((void**)&sc1,     g_sc1);
    cudaGetSymbolAddress((void**)&sh1,     g_sh1);
    cudaGetSymbolAddress((void**)&sc2,     g_sc2);
    cudaGetSymbolAddress((void**)&sh2,     g_sh2);
    cudaGetSymbolAddress((void**)&wpack,   g_wpack);
    cudaGetSymbolAddress((void**)&deg_a,   g_deg_a);
    cudaGetSymbolAddress((void**)&deg_b,   g_deg_b);
    cudaGetSymbolAddress((void**)&deg_c,   g_deg_c);
    cudaGetSymbolAddress((void**)&bsum_a,  g_bsum_a);
    cudaGetSymbolAddress((void**)&bsum_b,  g_bsum_b);
    cudaGetSymbolAddress((void**)&bsum_c,  g_bsum_c);
    cudaGetSymbolAddress((void**)&rp_resp, g_rp_resp);
    cudaGetSymbolAddress((void**)&rp_rev,  g_rp_rev);
    cudaGetSymbolAddress((void**)&rp_prec, g_rp_prec);
    cudaGetSymbolAddress((void**)&col_resp, g_col_resp);
    cudaGetSymbolAddress((void**)&col_rev,  g_col_rev);
    cudaGetSymbolAddress((void**)&col_prec, g_col_prec);

    const size_t W2 = 5 * 32768;   // layer-2 weight images offset

    // ---------- fork ----------
    cudaEventRecord(evRoot, 0);
    cudaStreamWaitEvent(s1, evRoot, 0);
    cudaStreamWaitEvent(s2, evRoot, 0);
    cudaStreamWaitEvent(s3, evRoot, 0);

    // s0: weight packing; s1: resp build; s2: rev build; s3: prec build
    pack_w<<<(10 * 16384 + 255) / 256, 256>>>(Wl_ri, Wr_ri, Wl_rs, Wr_rs, W_p, wpack);
    cudaEventRecord(evPack, 0);
    build_csr(resp_src, resp_dst, E1, NI, deg_a, bsum_a, rp_resp, col_resp, s1);
    build_csr(rev_src,  rev_dst,  E1, NS, deg_b, bsum_b, rp_rev,  col_rev,  s2);
    cudaEventRecord(evB2, s2);
    build_csr(prec_src, prec_dst, E2, NS, deg_c, bsum_c, rp_prec, col_prec, s3);
    cudaEventRecord(evB3, s3);

    // =================== layer 1 ===================
    // s1: item-GEMM (A1 = gather_resp(x_student) mean, A2 = x_item dense) -> bn_final
    cudaStreamWaitEvent(s1, evPack, 0);
    gemm_tc<<<(NI + 127) / 128, 512, SMEM_TC, s1>>>(
        x_student, rp_resp, col_resp, 0,
        x_item, nullptr, nullptr, 0,
        nullptr, nullptr, nullptr, 0,
        wpack + 0 * 32768, wpack + 1 * 32768, nullptr,
        nullptr, nullptr, -1, bl_ri, nullptr, 1.f, 1, bn, item, NI);
    bn_final<<<1, 128, 0, s1>>>(bn, bn_g, bn_b, sc1, sh1, 1.f / (float)NI);
    cudaEventRecord(evXi1, s1);

    // s0: stu-GEMM (A1 = gather_rev(x_item) mean, A2 = x_student dense,
    //               A3 = gather_prec(x_student) sum), scale 0.5 -> xs
    cudaStreamWaitEvent(0, evB2, 0);
    cudaStreamWaitEvent(0, evB3, 0);
    gemm_tc<<<(NS + 127) / 128, 512, SMEM_TC, 0>>>(
        x_item, rp_rev, col_rev, 0,
        x_student, nullptr, nullptr, 0,
        x_student, rp_prec, col_prec, 1,
        wpack + 2 * 32768, wpack + 3 * 32768, wpack + 4 * 32768,
        nullptr, nullptr, -1, bl_rs, b_p, 0.5f, 0, nullptr, xs, NS);
    cudaEventRecord(evXs1, 0);

    // =================== layer 2 ===================
    float* xi_out = out;                       // items first in output
    float* xs_out = out + (size_t)NI * D;

    // s1: item-GEMM layer 2 (A1 = gather_resp(xs) mean, A2 = item dense + BN affine)
    cudaStreamWaitEvent(s1, evXs1, 0);
    gemm_tc<<<(NI + 127) / 128, 512, SMEM_TC, s1>>>(
        xs, rp_resp, col_resp, 0,
        item, nullptr, nullptr, 0,
        nullptr, nullptr, nullptr, 0,
        wpack + W2 + 0 * 32768, wpack + W2 + 1 * 32768, nullptr,
        sc1, sh1, 1, bl_ri + D, nullptr, 1.f, 1, bn, item2, NI);
    bn_final<<<1, 128, 0, s1>>>(bn, bn_g + D, bn_b + D, sc2, sh2, 1.f / (float)NI);
    bn_apply<<<(NI * 32 + 255) / 256, 256, 0, s1>>>((const float4*)item2, sc2, sh2,
                                                    (float4*)xi_out, NI * 32);
    cudaEventRecord(evDone, s1);

    // s0: stu-GEMM layer 2 (A1 = gather_rev(item) mean+BN-affine, A2 = xs dense,
    //                       A3 = gather_prec(xs) sum) -> out students
    cudaStreamWaitEvent(0, evXi1, 0);          // item + sc1/sh1 ready (xs same stream)
    gemm_tc<<<(NS + 127) / 128, 512, SMEM_TC, 0>>>(
        item, rp_rev, col_rev, 2,
        xs, nullptr, nullptr, 0,
        xs, rp_prec, col_prec, 1,
        wpack + W2 + 2 * 32768, wpack + W2 + 3 * 32768, wpack + W2 + 4 * 32768,
        sc1, sh1, -1, bl_rs + D, b_p + D, 0.5f, 0, nullptr, xs_out, NS);

    // ---------- join ----------
    cudaStreamWaitEvent(0, evDone, 0);
}

// round 16
// speedup vs baseline: 1.1035x; 1.1035x over previous
#include <cuda_runtime.h>
#include <cuda_bf16.h>
#include <math.h>
#include <stdint.h>

#define NS 100000
#define NI 20000
#define D  128
#define L  2
#define E1 600000
#define E2 500000

// ---------------- scratch (static device globals: allocation-free) ----------------
__device__ float g_agg_s [(size_t)NS * D];
__device__ float g_agg_s2[(size_t)NS * D];   // layer-2 rev gather (no WAR on g_agg_s)
__device__ float g_agg_p[(size_t)NS * D];
__device__ float g_agg_i[(size_t)NI * D];
__device__ float g_part [(size_t)NS * D];    // dense-pass partial for stu-GEMMs
__device__ float g_xs  [(size_t)NS * D];
__device__ float g_item [(size_t)NI * D];   // layer-1 pre-BN item output
__device__ float g_item2[(size_t)NI * D];   // layer-2 pre-BN item output
__device__ float g_bn[2 * D];               // statically zero; bn_final re-zeroes after use
__device__ float g_sc1[D];
__device__ float g_sh1[D];
__device__ float g_sc2[D];
__device__ float g_sh2[D];
// packed weights: 10 matrices (2 layers x 5): hi image (16384 bf16) + lo image (16384 bf16)
__device__ __nv_bfloat16 g_wpack[10 * 32768];
// CSR structures (private scratch per edge list so builds can run concurrently)
__device__ int g_deg_a[NI + 2];
__device__ int g_deg_b[NS + 2];
__device__ int g_deg_c[NS + 2];
__device__ int g_bsum_a[128];
__device__ int g_bsum_b[128];
__device__ int g_bsum_c[128];
__device__ int g_rp_resp[NI + 1];
__device__ int g_rp_rev[NS + 1];
__device__ int g_rp_prec[NS + 1];
__device__ int g_col_resp[E1];
__device__ int g_col_rev[E1];
__device__ int g_col_prec[E2];

// ---------------- smem swizzle: 128 rows x 256B, 16B chunks XOR'd by row ----------------
__device__ __forceinline__ uint32_t sw_off(int row, int k) {
    return (uint32_t)(row * 256 + (((k >> 3) ^ (row & 7)) << 4) + ((k & 7) << 1));
}

__device__ __forceinline__ uint32_t s2u(const void* p) {
    uint32_t a;
    asm("{ .reg .u64 t; cvta.to.shared.u64 t, %1; cvt.u32.u64 %0, t; }" : "=r"(a) : "l"(p));
    return a;
}

__device__ __forceinline__ void ldsm4(uint32_t& r0, uint32_t& r1, uint32_t& r2, uint32_t& r3,
                                      uint32_t addr) {
    asm volatile("ldmatrix.sync.aligned.m8n8.x4.shared.b16 {%0,%1,%2,%3}, [%4];"
                 : "=r"(r0), "=r"(r1), "=r"(r2), "=r"(r3) : "r"(addr));
}

__device__ __forceinline__ void mma16816(float* c, uint32_t a0, uint32_t a1, uint32_t a2,
                                         uint32_t a3, uint32_t b0, uint32_t b1) {
    asm volatile("mma.sync.aligned.m16n8k16.row.col.f32.bf16.bf16.f32 "
                 "{%0,%1,%2,%3}, {%4,%5,%6,%7}, {%8,%9}, {%0,%1,%2,%3};"
                 : "+f"(c[0]), "+f"(c[1]), "+f"(c[2]), "+f"(c[3])
                 : "r"(a0), "r"(a1), "r"(a2), "r"(a3), "r"(b0), "r"(b1));
}

__device__ __forceinline__ void cpasync16(uint32_t s, const void* g) {
    asm volatile("cp.async.cg.shared.global [%0], [%1], 16;" :: "r"(s), "l"(g));
}

// ================= utility kernels =================
__global__ void zero_int(int* __restrict__ p, int n) {
    int i = blockIdx.x * blockDim.x + threadIdx.x;
    if (i < n) p[i] = 0;
}

// ================= CSR build (three-stage multi-block scan) =================
__global__ void hist_kernel(const int* __restrict__ dst, int E, int* __restrict__ deg) {
    int e = blockIdx.x * blockDim.x + threadIdx.x;
    if (e < E) atomicAdd(&deg[dst[e]], 1);
}

__global__ void scan_sum(const int* __restrict__ deg, int* __restrict__ bsum, int M) {
    __shared__ int wsum[8];
    int t = threadIdx.x;
    int base = blockIdx.x * 1024 + t * 4;
    int s = 0;
#pragma unroll
    for (int j = 0; j < 4; ++j) s += (base + j < M) ? deg[base + j] : 0;
#pragma unroll
    for (int o = 16; o > 0; o >>= 1) s += __shfl_down_sync(0xFFFFFFFFu, s, o);
    if ((t & 31) == 0) wsum[t >> 5] = s;
    __syncthreads();
    if (t == 0) {
        int r = 0;
#pragma unroll
        for (int w = 0; w < 8; ++w) r += wsum[w];
        bsum[blockIdx.x] = r;
    }
}

__global__ void scan_offsets(int* __restrict__ bsum, int nb) {
    if (threadIdx.x == 0 && blockIdx.x == 0) {
        int r = 0;
        for (int b = 0; b < nb; ++b) { int x = bsum[b]; bsum[b] = r; r += x; }
    }
}

__global__ void scan_block(const int* __restrict__ deg, const int* __restrict__ bsum,
                           int* __restrict__ rp, int M) {
    __shared__ int wsum[8];
    int t = threadIdx.x, lane = t & 31, wid = t >> 5;
    int base = blockIdx.x * 1024 + t * 4;
    int v[4];
#pragma unroll
    for (int j = 0; j < 4; ++j) v[j] = (base + j < M) ? deg[base + j] : 0;
    int tsum = v[0] + v[1] + v[2] + v[3];
    int incl = tsum;
#pragma unroll
    for (int o = 1; o < 32; o <<= 1) {
        int n = __shfl_up_sync(0xFFFFFFFFu, incl, o);
        if (lane >= o) incl += n;
    }
    if (lane == 31) wsum[wid] = incl;
    __syncthreads();
    if (t == 0) {
        int r = 0;
#pragma unroll
        for (int w = 0; w < 8; ++w) { int x = wsum[w]; wsum[w] = r; r += x; }
    }
    __syncthreads();
    int run = incl - tsum + wsum[wid] + bsum[blockIdx.x];
#pragma unroll
    for (int j = 0; j < 4; ++j) {
        if (base + j < M) { rp[base + j] = run; run += v[j]; }
    }
}

__global__ void fill_kernel(const int* __restrict__ src, const int* __restrict__ dst, int E,
                            const int* __restrict__ rp, int* __restrict__ fillc,
                            int* __restrict__ col) {
    int e = blockIdx.x * blockDim.x + threadIdx.x;
    if (e >= E) return;
    int d = dst[e];
    int pos = rp[d] + atomicAdd(&fillc[d], 1);
    col[pos] = src[e];
}

// ================= CSR aggregation: warp per destination row ==========
// mode 0: out[r] = (1/max(deg,1)) * sum X[col[i]]           (mean)
// mode 1: out[r] = coef * sum X[col[i]]                     (scaled sum)
// mode 2: out[r] = deg>0 ? mean(X[col[i]])*sc[c]+sh[c] : 0  (mean + folded BN affine)
__global__ void agg_csr(const float* __restrict__ X, const int* __restrict__ rp,
                        const int* __restrict__ col, int N, int mode, float coef,
                        const float* __restrict__ sc, const float* __restrict__ sh,
                        float* __restrict__ out) {
    int r = (int)((blockIdx.x * (unsigned)blockDim.x + threadIdx.x) >> 5);
    int lane = threadIdx.x & 31;
    if (r >= N) return;
    int beg = rp[r], end = rp[r + 1];
    float4 acc = make_float4(0.f, 0.f, 0.f, 0.f);
    int i = beg;
    int s_next = (i < end) ? __ldg(col + i) : 0;
    while (i < end) {
        int s = s_next;
        ++i;
        s_next = (i < end) ? __ldg(col + i) : 0;
        float4 v = __ldg((const float4*)(X + (size_t)s * D + lane * 4));
        acc.x += v.x; acc.y += v.y; acc.z += v.z; acc.w += v.w;
    }
    if (mode == 1) {
        acc.x *= coef; acc.y *= coef; acc.z *= coef; acc.w *= coef;
    } else {
        float m = 1.f / fmaxf((float)(end - beg), 1.f);
        acc.x *= m; acc.y *= m; acc.z *= m; acc.w *= m;
        if (mode == 2 && end > beg) {   // deg==0: reference yields 0 (affine must NOT apply)
            float4 s4 = __ldg((const float4*)(sc + lane * 4));
            float4 h4 = __ldg((const float4*)(sh + lane * 4));
            acc.x = acc.x * s4.x + h4.x;
            acc.y = acc.y * s4.y + h4.y;
            acc.z = acc.z * s4.z + h4.z;
            acc.w = acc.w * s4.w + h4.w;
        }
    }
    *(float4*)(out + (size_t)r * D + lane * 4) = acc;
}

// Pack all 10 weight matrices into bf16 hi/lo swizzled images ([n][k] rows of 256B).
__global__ void pack_w(const float* __restrict__ Wl_ri, const float* __restrict__ Wr_ri,
                       const float* __restrict__ Wl_rs, const float* __restrict__ Wr_rs,
                       const float* __restrict__ W_p, __nv_bfloat16* __restrict__ dst) {
    int gid = blockIdx.x * blockDim.x + threadIdx.x;
    if (gid >= 10 * 16384) return;
    int mid = gid >> 14;
    int idx = gid & 16383;
    int l = mid / 5, which = mid % 5;
    const float* src;
    switch (which) {
        case 0: src = Wl_ri; break;
        case 1: src = Wr_ri; break;
        case 2: src = Wl_rs; break;
        case 3: src = Wr_rs; break;
        default: src = W_p; break;
    }
    float a = src[(size_t)l * 16384 + idx];
    int n = idx >> 7, k = idx & 127;
    __nv_bfloat16 hi = __float2bfloat16(a);
    __nv_bfloat16 lo = __float2bfloat16(a - __bfloat162float(hi));
    uint32_t off = sw_off(n, k) >> 1;
    dst[(size_t)mid * 32768 + off] = hi;
    dst[(size_t)mid * 32768 + 16384 + off] = lo;
}

// ================= pipelined HMMA fused GEMM (512 threads, 4x4 warp grid, up to 3 passes) ====
// Out = f( sum_p Ap@Wp^T + partial + b1 [+ b2] ), bf16 3-term split per pass.
// W double-buffered via cp.async; A of next pass prefetched into registers during MMA.
// Optional per-column affine on pass aff_pass's A (folded batchnorm).
// Optional per-element partial added in epilogue (dense-pass split).
#define A_HI 0
#define A_LO 32768
#define W_BUF0 65536
#define W_BUF1 131072
#define BN_OFF 196608
#define SMEM_TC (196608 + 1024 + 16)

__device__ __forceinline__ void load_a_regs(const float* A, int m0, int M, int tid,
                                            float4 (&pa)[4][2]) {
#pragma unroll
    for (int it = 0; it < 4; ++it) {
        int idx = tid + it * 512;
        int row = idx >> 4;
        int k0 = (idx & 15) << 3;
        int m = m0 + row;
        float4 z = make_float4(0.f, 0.f, 0.f, 0.f);
        pa[it][0] = z; pa[it][1] = z;
        if (m < M) {
            const float* ap = A + (size_t)m * D + k0;
            pa[it][0] = __ldg((const float4*)ap);
            pa[it][1] = __ldg((const float4*)(ap + 4));
        }
    }
}

__global__ __launch_bounds__(512, 1)
void gemm_tc(const float* __restrict__ A1, const __nv_bfloat16* __restrict__ W1p,
             const float* __restrict__ A2, const __nv_bfloat16* __restrict__ W2p,
             const float* __restrict__ A3, const __nv_bfloat16* __restrict__ W3p,
             const float* __restrict__ aff_sc, const float* __restrict__ aff_sh, int aff_pass,
             const float* __restrict__ partial,
             const float* __restrict__ bias1, const float* __restrict__ bias2,
             float out_scale, int do_elu, float* __restrict__ bn,
             float* __restrict__ Out, int M) {
    extern __shared__ char smem[];
    const uint32_t sb = s2u(smem);
    float* bnS = (float*)(smem + BN_OFF);

    const int tid = threadIdx.x;
    const int w = tid >> 5, lane = tid & 31;
    const int wm = w >> 2, wn = w & 3;          // 4 x 4 warp grid
    const int m_base = wm * 32, n_base = wn * 32;
    const int m0 = blockIdx.x * 128;
    const int qr = lane >> 2, qc = lane & 3;

    if (tid < 256) bnS[tid] = 0.f;

    float acc[2][4][4];
#pragma unroll
    for (int a = 0; a < 2; ++a)
#pragma unroll
        for (int b = 0; b < 4; ++b)
#pragma unroll
            for (int c = 0; c < 4; ++c) acc[a][b][c] = 0.f;

    const float* As[3] = {A1, A2, A3};
    const __nv_bfloat16* Wsp[3] = {W1p, W2p, W3p};
    const int P = (A3 != nullptr) ? 3 : ((A2 != nullptr) ? 2 : 1);

    {
        const char* wg = (const char*)Wsp[0];
#pragma unroll
        for (int it = 0; it < 8; ++it) {
            int i = tid + it * 512;
            cpasync16(sb + W_BUF0 + i * 16, wg + (size_t)i * 16);
        }
        asm volatile("cp.async.commit_group;" ::: "memory");
    }
    float4 pa[4][2];
    load_a_regs(As[0], m0, M, tid, pa);

    for (int p = 0; p < P; ++p) {
        asm volatile("cp.async.wait_group 0;" ::: "memory");

#pragma unroll
        for (int it = 0; it < 4; ++it) {
            int idx = tid + it * 512;
            int row = idx >> 4;
            int k0 = (idx & 15) << 3;
            float av[8] = {pa[it][0].x, pa[it][0].y, pa[it][0].z, pa[it][0].w,
                           pa[it][1].x, pa[it][1].y, pa[it][1].z, pa[it][1].w};
            if (p == aff_pass) {
                float4 s0 = __ldg((const float4*)(aff_sc + k0));
                float4 s1 = __ldg((const float4*)(aff_sc + k0 + 4));
                float4 h0 = __ldg((const float4*)(aff_sh + k0));
                float4 h1 = __ldg((const float4*)(aff_sh + k0 + 4));
                av[0] = av[0] * s0.x + h0.x; av[1] = av[1] * s0.y + h0.y;
                av[2] = av[2] * s0.z + h0.z; av[3] = av[3] * s0.w + h0.w;
                av[4] = av[4] * s1.x + h1.x; av[5] = av[5] * s1.y + h1.y;
                av[6] = av[6] * s1.z + h1.z; av[7] = av[7] * s1.w + h1.w;
            }
            __nv_bfloat16 hv[8], lv[8];
#pragma unroll
            for (int j = 0; j < 8; ++j) {
                hv[j] = __float2bfloat16(av[j]);
                lv[j] = __float2bfloat16(av[j] - __bfloat162float(hv[j]));
            }
            uint32_t off = sw_off(row, k0);
            *(uint4*)(smem + A_HI + off) = *(uint4*)hv;
            *(uint4*)(smem + A_LO + off) = *(uint4*)lv;
        }
        __syncthreads();

        if (p + 1 < P) {
            const char* wg = (const char*)Wsp[p + 1];
            uint32_t wb = sb + (((p + 1) & 1) ? W_BUF1 : W_BUF0);
#pragma unroll
            for (int it = 0; it < 8; ++it) {
                int i = tid + it * 512;
                cpasync16(wb + i * 16, wg + (size_t)i * 16);
            }
            asm volatile("cp.async.commit_group;" ::: "memory");
            load_a_regs(As[p + 1], m0, M, tid, pa);
        }

        const uint32_t wbase = sb + ((p & 1) ? W_BUF1 : W_BUF0);
        for (int ks = 0; ks < 8; ++ks) {
            const int kc = ks * 16;
            uint32_t ah[2][4], al[2][4], bh[2][4], bl[2][4];
#pragma unroll
            for (int mt = 0; mt < 2; ++mt) {
                int row = m_base + mt * 16 + (lane & 15);
                int kk = kc + ((lane >> 4) << 3);
                uint32_t off = sw_off(row, kk);
                ldsm4(ah[mt][0], ah[mt][1], ah[mt][2], ah[mt][3], sb + A_HI + off);
                ldsm4(al[mt][0], al[mt][1], al[mt][2], al[mt][3], sb + A_LO + off);
            }
#pragma unroll
            for (int ng = 0; ng < 2; ++ng) {
                int n = n_base + ng * 16 + (lane & 7) + ((lane >> 4) << 3);
                int kk = kc + (((lane >> 3) & 1) << 3);
                uint32_t off = sw_off(n, kk);
                ldsm4(bh[ng][0], bh[ng][1], bh[ng][2], bh[ng][3], wbase + off);
                ldsm4(bl[ng][0], bl[ng][1], bl[ng][2], bl[ng][3], wbase + 32768 + off);
            }
#pragma unroll
            for (int mt = 0; mt < 2; ++mt)
#pragma unroll
                for (int ng = 0; ng < 2; ++ng) {
                    mma16816(acc[mt][ng * 2 + 0], ah[mt][0], ah[mt][1], ah[mt][2], ah[mt][3],
                             bh[ng][0], bh[ng][1]);
                    mma16816(acc[mt][ng * 2 + 1], ah[mt][0], ah[mt][1], ah[mt][2], ah[mt][3],
                             bh[ng][2], bh[ng][3]);
                    mma16816(acc[mt][ng * 2 + 0], ah[mt][0], ah[mt][1], ah[mt][2], ah[mt][3],
                             bl[ng][0], bl[ng][1]);
                    mma16816(acc[mt][ng * 2 + 1], ah[mt][0], ah[mt][1], ah[mt][2], ah[mt][3],
                             bl[ng][2], bl[ng][3]);
                    mma16816(acc[mt][ng * 2 + 0], al[mt][0], al[mt][1], al[mt][2], al[mt][3],
                             bh[ng][0], bh[ng][1]);
                    mma16816(acc[mt][ng * 2 + 1], al[mt][0], al[mt][1], al[mt][2], al[mt][3],
                             bh[ng][2], bh[ng][3]);
                }
        }
        __syncthreads();
    }

    // ---------------- epilogue ----------------
    float bcol[8];
#pragma unroll
    for (int nt = 0; nt < 4; ++nt)
#pragma unroll
        for (int par = 0; par < 2; ++par) {
            int c = n_base + nt * 8 + qc * 2 + par;
            float bb = 0.f;
            if (bias1 != nullptr) bb += bias1[c];
            if (bias2 != nullptr) bb += bias2[c];
            bcol[nt * 2 + par] = bb;
        }

    float cs[8], cq[8];
#pragma unroll
    for (int j = 0; j < 8; ++j) { cs[j] = 0.f; cq[j] = 0.f; }

#pragma unroll
    for (int mt = 0; mt < 2; ++mt)
#pragma unroll
        for (int jh = 0; jh < 2; ++jh) {
            int m = m0 + m_base + mt * 16 + qr + jh * 8;
            bool valid = (m < M);
            float2 part[4];
            if (valid && partial != nullptr) {
                const float* pp = partial + (size_t)m * D + n_base + qc * 2;
#pragma unroll
                for (int nt = 0; nt < 4; ++nt) part[nt] = *(const float2*)(pp + nt * 8);
            } else {
#pragma unroll
                for (int nt = 0; nt < 4; ++nt) part[nt] = make_float2(0.f, 0.f);
            }
            float2 vals[4];
#pragma unroll
            for (int nt = 0; nt < 4; ++nt) {
                float v0 = acc[mt][nt][jh * 2 + 0] + bcol[nt * 2 + 0] + part[nt].x;
                float v1 = acc[mt][nt][jh * 2 + 1] + bcol[nt * 2 + 1] + part[nt].y;
                if (do_elu) {
                    v0 = (v0 > 0.f) ? v0 : expm1f(v0);
                    v1 = (v1 > 0.f) ? v1 : expm1f(v1);
                }
                v0 *= out_scale; v1 *= out_scale;
                vals[nt] = make_float2(v0, v1);
                if (valid) {
                    cs[nt * 2 + 0] += v0; cq[nt * 2 + 0] += v0 * v0;
                    cs[nt * 2 + 1] += v1; cq[nt * 2 + 1] += v1 * v1;
                }
            }
            if (valid) {
                float* op = Out + (size_t)m * D + n_base + qc * 2;
#pragma unroll
                for (int nt = 0; nt < 4; ++nt)
                    *(float2*)(op + nt * 8) = vals[nt];
            }
        }

    if (bn != nullptr) {
#pragma unroll
        for (int j = 0; j < 8; ++j) {
#pragma unroll
            for (int o = 16; o >= 4; o >>= 1) {
                cs[j] += __shfl_down_sync(0xFFFFFFFFu, cs[j], o);
                cq[j] += __shfl_down_sync(0xFFFFFFFFu, cq[j], o);
            }
        }
        if (lane < 4) {
#pragma unroll
            for (int nt = 0; nt < 4; ++nt)
#pragma unroll
                for (int par = 0; par < 2; ++par) {
                    int c = n_base + nt * 8 + lane * 2 + par;
                    atomicAdd(&bnS[c], cs[nt * 2 + par]);
                    atomicAdd(&bnS[128 + c], cq[nt * 2 + par]);
                }
        }
        __syncthreads();
        if (tid < 256) atomicAdd(&bn[tid], bnS[tid]);
    }
}

// ================= batchnorm =================
__global__ void bn_final(float* __restrict__ bn, const float* __restrict__ g,
                         const float* __restrict__ b, float* __restrict__ scale,
                         float* __restrict__ shift, float invN) {
    int c = threadIdx.x;
    float m = bn[c] * invN;
    float var = bn[D + c] * invN - m * m;
    float rs = rsqrtf(var + 1e-5f);
    float sc = g[c] * rs;
    scale[c] = sc;
    shift[c] = b[c] - m * sc;
    bn[c] = 0.f;
    bn[D + c] = 0.f;
}

__global__ void bn_apply(const float4* __restrict__ x, const float* __restrict__ scale,
                         const float* __restrict__ shift, float4* __restrict__ y, int n4) {
    int i = blockIdx.x * blockDim.x + threadIdx.x;
    if (i >= n4) return;
    int c = (i & 31) * 4;
    float4 v = x[i];
    v.x = v.x * scale[c + 0] + shift[c + 0];
    v.y = v.y * scale[c + 1] + shift[c + 1];
    v.z = v.z * scale[c + 2] + shift[c + 2];
    v.w = v.w * scale[c + 3] + shift[c + 3];
    y[i] = v;
}

// ================= host =================
static inline void launch_gemm(const float* A1, const __nv_bfloat16* W1p,
                               const float* A2, const __nv_bfloat16* W2p,
                               const float* A3, const __nv_bfloat16* W3p,
                               const float* aff_sc, const float* aff_sh, int aff_pass,
                               const float* partial,
                               const float* b1, const float* b2,
                               float out_scale, int do_elu, float* bn,
                               float* Out, int M, cudaStream_t st) {
    gemm_tc<<<(M + 127) / 128, 512, SMEM_TC, st>>>(A1, W1p, A2, W2p, A3, W3p,
                                                   aff_sc, aff_sh, aff_pass, partial, b1, b2,
                                                   out_scale, do_elu, bn, Out, M);
}

static inline void build_csr(const int* src, const int* dst, int E, int N,
                             int* deg, int* bsum, int* rp, int* col, cudaStream_t st) {
    int M = N + 1;
    int nb = (M + 1023) / 1024;
    zero_int<<<(M + 255) / 256, 256, 0, st>>>(deg, M);
    hist_kernel<<<(E + 255) / 256, 256, 0, st>>>(dst, E, deg);
    scan_sum<<<nb, 256, 0, st>>>(deg, bsum, M);
    scan_offsets<<<1, 32, 0, st>>>(bsum, nb);
    scan_block<<<nb, 256, 0, st>>>(deg, bsum, rp, M);
    zero_int<<<(N + 255) / 256, 256, 0, st>>>(deg, N);
    fill_kernel<<<(E + 255) / 256, 256, 0, st>>>(src, dst, E, rp, deg, col);
}

extern "C" void kernel_launch(void* const* d_in, const int* in_sizes, int n_in,
                              void* d_out, int out_size) {
    const float* x_student = (const float*)d_in[0];
    const float* x_item    = (const float*)d_in[1];
    const float* Wl_ri = (const float*)d_in[2];
    const float* bl_ri = (const float*)d_in[3];
    const float* Wr_ri = (const float*)d_in[4];
    const float* Wl_rs = (const float*)d_in[5];
    const float* bl_rs = (const float*)d_in[6];
    const float* Wr_rs = (const float*)d_in[7];
    const float* W_p   = (const float*)d_in[8];
    const float* b_p   = (const float*)d_in[9];
    const float* bn_g  = (const float*)d_in[10];
    const float* bn_b  = (const float*)d_in[11];
    const int* resp_src = (const int*)d_in[12];
    const int* resp_dst = (const int*)d_in[13];
    const int* rev_src  = (const int*)d_in[14];
    const int* rev_dst  = (const int*)d_in[15];
    const int* prec_src = (const int*)d_in[16];
    const int* prec_dst = (const int*)d_in[17];
    float* out = (float*)d_out;

    static int configured = 0;
    static cudaStream_t s1, s2, s3;
    static cudaEvent_t evRoot, evPack, evAggS1, evAggP1, evAggS2, evAggP2,
                       evXs1, evXi1, evDone1;
    if (!configured) {
        cudaFuncSetAttribute(gemm_tc, cudaFuncAttributeMaxDynamicSharedMemorySize, SMEM_TC);
        cudaStreamCreateWithFlags(&s1, cudaStreamNonBlocking);
        cudaStreamCreateWithFlags(&s2, cudaStreamNonBlocking);
        cudaStreamCreateWithFlags(&s3, cudaStreamNonBlocking);
        cudaEventCreateWithFlags(&evRoot, cudaEventDisableTiming);
        cudaEventCreateWithFlags(&evPack, cudaEventDisableTiming);
        cudaEventCreateWithFlags(&evAggS1, cudaEventDisableTiming);
        cudaEventCreateWithFlags(&evAggP1, cudaEventDisableTiming);
        cudaEventCreateWithFlags(&evAggS2, cudaEventDisableTiming);
        cudaEventCreateWithFlags(&evAggP2, cudaEventDisableTiming);
        cudaEventCreateWithFlags(&evXs1, cudaEventDisableTiming);
        cudaEventCreateWithFlags(&evXi1, cudaEventDisableTiming);
        cudaEventCreateWithFlags(&evDone1, cudaEventDisableTiming);
        configured = 1;
    }

    float *agg_s, *agg_s2, *agg_p, *agg_i, *part, *xs, *item, *item2, *bn;
    float *sc1, *sh1, *sc2, *sh2;
    __nv_bfloat16* wpack;
    int *deg_a, *deg_b, *deg_c, *bsum_a, *bsum_b, *bsum_c;
    int *rp_resp, *rp_rev, *rp_prec, *col_resp, *col_rev, *col_prec;
    cudaGetSymbolAddress((void**)&agg_s,   g_agg_s);
    cudaGetSymbolAddress((void**)&agg_s2,  g_agg_s2);
    cudaGetSymbolAddress((void**)&agg_p,   g_agg_p);
    cudaGetSymbolAddress((void**)&agg_i,   g_agg_i);
    cudaGetSymbolAddress((void**)&part,    g_part);
    cudaGetSymbolAddress((void**)&xs,      g_xs);
    cudaGetSymbolAddress((void**)&item,    g_item);
    cudaGetSymbolAddress((void**)&item2,   g_item2);
    cudaGetSymbolAddress((void**)&bn,      g_bn);
    cudaGetSymbolAddress((void**)&sc1,     g_sc1);
    cudaGetSymbolAddress((void**)&sh1,     g_sh1);
    cudaGetSymbolAddress((void**)&sc2,     g_sc2);
    cudaGetSymbolAddress((void**)&sh2,     g_sh2);
    cudaGetSymbolAddress((void**)&wpack,   g_wpack);
    cudaGetSymbolAddress((void**)&deg_a,   g_deg_a);
    cudaGetSymbolAddress((void**)&deg_b,   g_deg_b);
    cudaGetSymbolAddress((void**)&deg_c,   g_deg_c);
    cudaGetSymbolAddress((void**)&bsum_a,  g_bsum_a);
    cudaGetSymbolAddress((void**)&bsum_b,  g_bsum_b);
    cudaGetSymbolAddress((void**)&bsum_c,  g_bsum_c);
    cudaGetSymbolAddress((void**)&rp_resp, g_rp_resp);
    cudaGetSymbolAddress((void**)&rp_rev,  g_rp_rev);
    cudaGetSymbolAddress((void**)&rp_prec, g_rp_prec);
    cudaGetSymbolAddress((void**)&col_resp, g_col_resp);
    cudaGetSymbolAddress((void**)&col_rev,  g_col_rev);
    cudaGetSymbolAddress((void**)&col_prec, g_col_prec);

    const size_t W2off = 5 * 32768;   // layer-2 weight images

    // ---------- fork ----------
    cudaEventRecord(evRoot, 0);
    cudaStreamWaitEvent(s1, evRoot, 0);
    cudaStreamWaitEvent(s2, evRoot, 0);
    cudaStreamWaitEvent(s3, evRoot, 0);

    // stream 0: weight packing + DENSE stu pass K1 (overlaps builds + aggs);
    // s1/s2/s3: the three CSR builds (private scratch)
    pack_w<<<(10 * 16384 + 255) / 256, 256>>>(Wl_ri, Wr_ri, Wl_rs, Wr_rs, W_p, wpack);
    cudaEventRecord(evPack, 0);
    build_csr(resp_src, resp_dst, E1, NI, deg_a, bsum_a, rp_resp, col_resp, s1);
    build_csr(rev_src,  rev_dst,  E1, NS, deg_b, bsum_b, rp_rev,  col_rev,  s2);
    build_csr(prec_src, prec_dst, E2, NS, deg_c, bsum_c, rp_prec, col_prec, s3);

    cudaStreamWaitEvent(s1, evPack, 0);   // item-GEMM needs weights

    // s0: K1_L1 = x_student @ Wr_rs^T -> part (no deps beyond pack, same stream)
    launch_gemm(x_student, wpack + 3 * 32768, nullptr, nullptr, nullptr, nullptr,
                nullptr, nullptr, -1, nullptr, nullptr, nullptr,
                1.f, 0, nullptr, part, NS, 0);

    // =================== layer 1 ===================
    // s2: agg_s = mean_rev(x_item)
    agg_csr<<<(NS * 32 + 255) / 256, 256, 0, s2>>>(x_item, rp_rev, col_rev, NS, 0, 0.f,
                                                   nullptr, nullptr, agg_s);
    cudaEventRecord(evAggS1, s2);
    // s3: agg_p = sum_prec(x_student)
    agg_csr<<<(NS * 32 + 255) / 256, 256, 0, s3>>>(x_student, rp_prec, col_prec, NS, 1, 1.f,
                                                   nullptr, nullptr, agg_p);
    cudaEventRecord(evAggP1, s3);

    // s1: item chain: agg_i -> item-GEMM (pre-BN) -> bn_final (sc1/sh1)
    agg_csr<<<(NI * 32 + 255) / 256, 256, 0, s1>>>(x_student, rp_resp, col_resp, NI, 0, 0.f,
                                                   nullptr, nullptr, agg_i);
    launch_gemm(agg_i, wpack + 0 * 32768, x_item, wpack + 1 * 32768, nullptr, nullptr,
                nullptr, nullptr, -1, nullptr, bl_ri, nullptr, 1.f, 1, bn, item, NI, s1);
    bn_final<<<1, 128, 0, s1>>>(bn, bn_g, bn_b, sc1, sh1, 1.f / (float)NI);
    cudaEventRecord(evXi1, s1);

    // s0: K2_L1 = 0.5*(agg_s@Wl_rs^T + agg_p@W_p^T + part + bl_rs + b_p) -> xs
    cudaStreamWaitEvent(0, evAggS1, 0);
    cudaStreamWaitEvent(0, evAggP1, 0);
    launch_gemm(agg_s, wpack + 2 * 32768, agg_p, wpack + 4 * 32768, nullptr, nullptr,
                nullptr, nullptr, -1, part, bl_rs, b_p, 0.5f, 0, nullptr, xs, NS, 0);
    cudaEventRecord(evXs1, 0);

    // =================== layer 2 ===================
    float* xi_out = out;                       // items first in output
    float* xs_out = out + (size_t)NI * D;

    // s0: K1_L2 = xs @ Wr_rs2^T -> part (runs concurrently with layer-2 aggs)
    launch_gemm(xs, wpack + W2off + 3 * 32768, nullptr, nullptr, nullptr, nullptr,
                nullptr, nullptr, -1, nullptr, nullptr, nullptr,
                1.f, 0, nullptr, part, NS, 0);

    // s2: agg_s2 = mean_rev(item) with folded BN (separate buffer: no WAR wait)
    cudaStreamWaitEvent(s2, evXi1, 0);
    agg_csr<<<(NS * 32 + 255) / 256, 256, 0, s2>>>(item, rp_rev, col_rev, NS, 2, 0.f,
                                                   sc1, sh1, agg_s2);
    cudaEventRecord(evAggS2, s2);

    // s3: agg_p = sum_prec(xs) (WAR on agg_p cleared by evXs1)
    cudaStreamWaitEvent(s3, evXs1, 0);
    agg_csr<<<(NS * 32 + 255) / 256, 256, 0, s3>>>(xs, rp_prec, col_prec, NS, 1, 1.f,
                                                   nullptr, nullptr, agg_p);
    cudaEventRecord(evAggP2, s3);

    // s1: item chain layer 2: agg_i(xs) -> GEMM (A2 = item with folded BN affine) -> bn -> out
    cudaStreamWaitEvent(s1, evXs1, 0);
    agg_csr<<<(NI * 32 + 255) / 256, 256, 0, s1>>>(xs, rp_resp, col_resp, NI, 0, 0.f,
                                                   nullptr, nullptr, agg_i);
    launch_gemm(agg_i, wpack + W2off + 0 * 32768, item, wpack + W2off + 1 * 32768,
                nullptr, nullptr, sc1, sh1, 1, nullptr,
                bl_ri + D, nullptr, 1.f, 1, bn, item2, NI, s1);
    bn_final<<<1, 128, 0, s1>>>(bn, bn_g + D, bn_b + D, sc2, sh2, 1.f / (float)NI);
    bn_apply<<<(NI * 32 + 255) / 256, 256, 0, s1>>>((const float4*)item2, sc2, sh2,
                                                    (float4*)xi_out, NI * 32);
    cudaEventRecord(evDone1, s1);

    // s0: K2_L2 = 0.5*(agg_s2@Wl_rs2^T + agg_p@W_p2^T + part + biases) -> out students
    cudaStreamWaitEvent(0, evAggS2, 0);
    cudaStreamWaitEvent(0, evAggP2, 0);
    launch_gemm(agg_s2, wpack + W2off + 2 * 32768, agg_p, wpack + W2off + 4 * 32768,
                nullptr, nullptr, nullptr, nullptr, -1, part,
                bl_rs + D, b_p + D, 0.5f, 0, nullptr, xs_out, NS, 0);

    // ---------- join all branches back to stream 0 ----------
    cudaStreamWaitEvent(0, evDone1, 0);
}

// round 17
// speedup vs baseline: 1.2154x; 1.1014x over previous
#include <cuda_runtime.h>
#include <cuda_bf16.h>
#include <math.h>
#include <stdint.h>

#define NS 100000
#define NI 20000
#define D  128
#define L  2
#define E1 600000
#define E2 500000

// ---------------- scratch (static device globals: allocation-free) ----------------
__device__ float g_agg_s [(size_t)NS * D];
__device__ float g_agg_s2[(size_t)NS * D];   // layer-2 rev gather (removes WAR on g_agg_s)
__device__ float g_agg_p[(size_t)NS * D];
__device__ float g_agg_i[(size_t)NI * D];
__device__ float g_xs  [(size_t)NS * D];
__device__ float g_item [(size_t)NI * D];   // layer-1 pre-BN item output
__device__ float g_item2[(size_t)NI * D];   // layer-2 pre-BN item output
__device__ float g_bn[2 * D];               // statically zero; bn_final re-zeroes after use
__device__ float g_sc1[D];
__device__ float g_sh1[D];
__device__ float g_sc2[D];
__device__ float g_sh2[D];
// packed weights: 10 matrices (2 layers x 5): hi image (16384 bf16) + lo image (16384 bf16)
__device__ __nv_bfloat16 g_wpack[10 * 32768];
// CSR structures. deg arrays are statically zero; hist increments, fill decrements
// back to zero -> invariant holds across graph replays with NO zeroing kernels.
__device__ int g_deg_a[NI + 2];
__device__ int g_deg_b[NS + 2];
__device__ int g_deg_c[NS + 2];
__device__ int g_bsum_a[128];
__device__ int g_bsum_b[128];
__device__ int g_bsum_c[128];
__device__ int g_rp_resp[NI + 1];
__device__ int g_rp_rev[NS + 1];
__device__ int g_rp_prec[NS + 1];
__device__ int g_col_resp[E1];
__device__ int g_col_rev[E1];
__device__ int g_col_prec[E2];

// ---------------- smem swizzle: 128 rows x 256B, 16B chunks XOR'd by row ----------------
__device__ __forceinline__ uint32_t sw_off(int row, int k) {
    return (uint32_t)(row * 256 + (((k >> 3) ^ (row & 7)) << 4) + ((k & 7) << 1));
}

__device__ __forceinline__ uint32_t s2u(const void* p) {
    uint32_t a;
    asm("{ .reg .u64 t; cvta.to.shared.u64 t, %1; cvt.u32.u64 %0, t; }" : "=r"(a) : "l"(p));
    return a;
}

__device__ __forceinline__ void ldsm4(uint32_t& r0, uint32_t& r1, uint32_t& r2, uint32_t& r3,
                                      uint32_t addr) {
    asm volatile("ldmatrix.sync.aligned.m8n8.x4.shared.b16 {%0,%1,%2,%3}, [%4];"
                 : "=r"(r0), "=r"(r1), "=r"(r2), "=r"(r3) : "r"(addr));
}

__device__ __forceinline__ void mma16816(float* c, uint32_t a0, uint32_t a1, uint32_t a2,
                                         uint32_t a3, uint32_t b0, uint32_t b1) {
    asm volatile("mma.sync.aligned.m16n8k16.row.col.f32.bf16.bf16.f32 "
                 "{%0,%1,%2,%3}, {%4,%5,%6,%7}, {%8,%9}, {%0,%1,%2,%3};"
                 : "+f"(c[0]), "+f"(c[1]), "+f"(c[2]), "+f"(c[3])
                 : "r"(a0), "r"(a1), "r"(a2), "r"(a3), "r"(b0), "r"(b1));
}

__device__ __forceinline__ void cpasync16(uint32_t s, const void* g) {
    asm volatile("cp.async.cg.shared.global [%0], [%1], 16;" :: "r"(s), "l"(g));
}

// ================= CSR build (no zeroing kernels; deg is self-restoring) =================
__global__ void hist_kernel(const int* __restrict__ dst, int E, int* __restrict__ deg) {
    int e = blockIdx.x * blockDim.x + threadIdx.x;
    if (e < E) atomicAdd(&deg[dst[e]], 1);
}

__global__ void scan_sum(const int* __restrict__ deg, int* __restrict__ bsum, int M) {
    __shared__ int wsum[8];
    int t = threadIdx.x;
    int base = blockIdx.x * 1024 + t * 4;
    int s = 0;
#pragma unroll
    for (int j = 0; j < 4; ++j) s += (base + j < M) ? deg[base + j] : 0;
#pragma unroll
    for (int o = 16; o > 0; o >>= 1) s += __shfl_down_sync(0xFFFFFFFFu, s, o);
    if ((t & 31) == 0) wsum[t >> 5] = s;
    __syncthreads();
    if (t == 0) {
        int r = 0;
#pragma unroll
        for (int w = 0; w < 8; ++w) r += wsum[w];
        bsum[blockIdx.x] = r;
    }
}

__global__ void scan_offsets(int* __restrict__ bsum, int nb) {
    if (threadIdx.x == 0 && blockIdx.x == 0) {
        int r = 0;
        for (int b = 0; b < nb; ++b) { int x = bsum[b]; bsum[b] = r; r += x; }
    }
}

__global__ void scan_block(const int* __restrict__ deg, const int* __restrict__ bsum,
                           int* __restrict__ rp, int M) {
    __shared__ int wsum[8];
    int t = threadIdx.x, lane = t & 31, wid = t >> 5;
    int base = blockIdx.x * 1024 + t * 4;
    int v[4];
#pragma unroll
    for (int j = 0; j < 4; ++j) v[j] = (base + j < M) ? deg[base + j] : 0;
    int tsum = v[0] + v[1] + v[2] + v[3];
    int incl = tsum;
#pragma unroll
    for (int o = 1; o < 32; o <<= 1) {
        int n = __shfl_up_sync(0xFFFFFFFFu, incl, o);
        if (lane >= o) incl += n;
    }
    if (lane == 31) wsum[wid] = incl;
    __syncthreads();
    if (t == 0) {
        int r = 0;
#pragma unroll
        for (int w = 0; w < 8; ++w) { int x = wsum[w]; wsum[w] = r; r += x; }
    }
    __syncthreads();
    int run = incl - tsum + wsum[wid] + bsum[blockIdx.x];
#pragma unroll
    for (int j = 0; j < 4; ++j) {
        if (base + j < M) { rp[base + j] = run; run += v[j]; }
    }
}

// fill uses atomicSub on deg: slot = deg[d]-1 .. 0 (reversed order, sums unaffected);
// leaves deg == 0 afterwards, restoring the replay invariant with no zero kernel.
__global__ void fill_kernel(const int* __restrict__ src, const int* __restrict__ dst, int E,
                            const int* __restrict__ rp, int* __restrict__ deg,
                            int* __restrict__ col) {
    int e = blockIdx.x * blockDim.x + threadIdx.x;
    if (e >= E) return;
    int d = dst[e];
    int slot = atomicAdd(&deg[d], -1) - 1;
    col[rp[d] + slot] = src[e];
}

// ================= CSR aggregation: warp per destination row ==========
// mode 0: out[r] = (1/max(deg,1)) * sum X[col[i]]           (mean)
// mode 1: out[r] = coef * sum X[col[i]]                     (scaled sum)
// mode 2: out[r] = deg>0 ? mean(X[col[i]])*sc[c]+sh[c] : 0  (mean + folded BN affine)
__global__ void agg_csr(const float* __restrict__ X, const int* __restrict__ rp,
                        const int* __restrict__ col, int N, int mode, float coef,
                        const float* __restrict__ sc, const float* __restrict__ sh,
                        float* __restrict__ out) {
    int r = (int)((blockIdx.x * (unsigned)blockDim.x + threadIdx.x) >> 5);
    int lane = threadIdx.x & 31;
    if (r >= N) return;
    int beg = rp[r], end = rp[r + 1];
    float4 acc = make_float4(0.f, 0.f, 0.f, 0.f);
    int i = beg;
    int s_next = (i < end) ? __ldg(col + i) : 0;
    while (i < end) {
        int s = s_next;
        ++i;
        s_next = (i < end) ? __ldg(col + i) : 0;
        float4 v = __ldg((const float4*)(X + (size_t)s * D + lane * 4));
        acc.x += v.x; acc.y += v.y; acc.z += v.z; acc.w += v.w;
    }
    if (mode == 1) {
        acc.x *= coef; acc.y *= coef; acc.z *= coef; acc.w *= coef;
    } else {
        float m = 1.f / fmaxf((float)(end - beg), 1.f);
        acc.x *= m; acc.y *= m; acc.z *= m; acc.w *= m;
        if (mode == 2 && end > beg) {   // deg==0: reference yields 0 (affine must NOT apply)
            float4 s4 = __ldg((const float4*)(sc + lane * 4));
            float4 h4 = __ldg((const float4*)(sh + lane * 4));
            acc.x = acc.x * s4.x + h4.x;
            acc.y = acc.y * s4.y + h4.y;
            acc.z = acc.z * s4.z + h4.z;
            acc.w = acc.w * s4.w + h4.w;
        }
    }
    *(float4*)(out + (size_t)r * D + lane * 4) = acc;
}

// Pack all 10 weight matrices into bf16 hi/lo swizzled images ([n][k] rows of 256B).
__global__ void pack_w(const float* __restrict__ Wl_ri, const float* __restrict__ Wr_ri,
                       const float* __restrict__ Wl_rs, const float* __restrict__ Wr_rs,
                       const float* __restrict__ W_p, __nv_bfloat16* __restrict__ dst) {
    int gid = blockIdx.x * blockDim.x + threadIdx.x;
    if (gid >= 10 * 16384) return;
    int mid = gid >> 14;
    int idx = gid & 16383;
    int l = mid / 5, which = mid % 5;
    const float* src;
    switch (which) {
        case 0: src = Wl_ri; break;
        case 1: src = Wr_ri; break;
        case 2: src = Wl_rs; break;
        case 3: src = Wr_rs; break;
        default: src = W_p; break;
    }
    float a = src[(size_t)l * 16384 + idx];
    int n = idx >> 7, k = idx & 127;
    __nv_bfloat16 hi = __float2bfloat16(a);
    __nv_bfloat16 lo = __float2bfloat16(a - __bfloat162float(hi));
    uint32_t off = sw_off(n, k) >> 1;
    dst[(size_t)mid * 32768 + off] = hi;
    dst[(size_t)mid * 32768 + 16384 + off] = lo;
}

// ================= pipelined HMMA fused GEMM (512 threads, 4x4 warp grid, up to 3 passes) ====
#define A_HI 0
#define A_LO 32768
#define W_BUF0 65536
#define W_BUF1 131072
#define BN_OFF 196608
#define SMEM_TC (196608 + 1024 + 16)

__device__ __forceinline__ void load_a_regs(const float* A, int m0, int M, int tid,
                                            float4 (&pa)[4][2]) {
#pragma unroll
    for (int it = 0; it < 4; ++it) {
        int idx = tid + it * 512;
        int row = idx >> 4;
        int k0 = (idx & 15) << 3;
        int m = m0 + row;
        float4 z = make_float4(0.f, 0.f, 0.f, 0.f);
        pa[it][0] = z; pa[it][1] = z;
        if (m < M) {
            const float* ap = A + (size_t)m * D + k0;
            pa[it][0] = __ldg((const float4*)ap);
            pa[it][1] = __ldg((const float4*)(ap + 4));
        }
    }
}

__global__ __launch_bounds__(512, 1)
void gemm_tc(const float* __restrict__ A1, const __nv_bfloat16* __restrict__ W1p,
             const float* __restrict__ A2, const __nv_bfloat16* __restrict__ W2p,
             const float* __restrict__ A3, const __nv_bfloat16* __restrict__ W3p,
             const float* __restrict__ aff_sc, const float* __restrict__ aff_sh, int aff_pass,
             const float* __restrict__ bias1, const float* __restrict__ bias2,
             float out_scale, int do_elu, float* __restrict__ bn,
             float* __restrict__ Out, int M) {
    extern __shared__ char smem[];
    const uint32_t sb = s2u(smem);
    float* bnS = (float*)(smem + BN_OFF);

    const int tid = threadIdx.x;
    const int w = tid >> 5, lane = tid & 31;
    const int wm = w >> 2, wn = w & 3;          // 4 x 4 warp grid
    const int m_base = wm * 32, n_base = wn * 32;
    const int m0 = blockIdx.x * 128;
    const int qr = lane >> 2, qc = lane & 3;

    if (tid < 256) bnS[tid] = 0.f;

    float acc[2][4][4];
#pragma unroll
    for (int a = 0; a < 2; ++a)
#pragma unroll
        for (int b = 0; b < 4; ++b)
#pragma unroll
            for (int c = 0; c < 4; ++c) acc[a][b][c] = 0.f;

    const float* As[3] = {A1, A2, A3};
    const __nv_bfloat16* Wsp[3] = {W1p, W2p, W3p};
    const int P = (A3 != nullptr) ? 3 : ((A2 != nullptr) ? 2 : 1);

    {
        const char* wg = (const char*)Wsp[0];
#pragma unroll
        for (int it = 0; it < 8; ++it) {
            int i = tid + it * 512;
            cpasync16(sb + W_BUF0 + i * 16, wg + (size_t)i * 16);
        }
        asm volatile("cp.async.commit_group;" ::: "memory");
    }
    float4 pa[4][2];
    load_a_regs(As[0], m0, M, tid, pa);

    for (int p = 0; p < P; ++p) {
        asm volatile("cp.async.wait_group 0;" ::: "memory");

#pragma unroll
        for (int it = 0; it < 4; ++it) {
            int idx = tid + it * 512;
            int row = idx >> 4;
            int k0 = (idx & 15) << 3;
            float av[8] = {pa[it][0].x, pa[it][0].y, pa[it][0].z, pa[it][0].w,
                           pa[it][1].x, pa[it][1].y, pa[it][1].z, pa[it][1].w};
            if (p == aff_pass) {
                float4 s0 = __ldg((const float4*)(aff_sc + k0));
                float4 s1 = __ldg((const float4*)(aff_sc + k0 + 4));
                float4 h0 = __ldg((const float4*)(aff_sh + k0));
                float4 h1 = __ldg((const float4*)(aff_sh + k0 + 4));
                av[0] = av[0] * s0.x + h0.x; av[1] = av[1] * s0.y + h0.y;
                av[2] = av[2] * s0.z + h0.z; av[3] = av[3] * s0.w + h0.w;
                av[4] = av[4] * s1.x + h1.x; av[5] = av[5] * s1.y + h1.y;
                av[6] = av[6] * s1.z + h1.z; av[7] = av[7] * s1.w + h1.w;
            }
            __nv_bfloat16 hv[8], lv[8];
#pragma unroll
            for (int j = 0; j < 8; ++j) {
                hv[j] = __float2bfloat16(av[j]);
                lv[j] = __float2bfloat16(av[j] - __bfloat162float(hv[j]));
            }
            uint32_t off = sw_off(row, k0);
            *(uint4*)(smem + A_HI + off) = *(uint4*)hv;
            *(uint4*)(smem + A_LO + off) = *(uint4*)lv;
        }
        __syncthreads();

        if (p + 1 < P) {
            const char* wg = (const char*)Wsp[p + 1];
            uint32_t wb = sb + (((p + 1) & 1) ? W_BUF1 : W_BUF0);
#pragma unroll
            for (int it = 0; it < 8; ++it) {
                int i = tid + it * 512;
                cpasync16(wb + i * 16, wg + (size_t)i * 16);
            }
            asm volatile("cp.async.commit_group;" ::: "memory");
            load_a_regs(As[p + 1], m0, M, tid, pa);
        }

        const uint32_t wbase = sb + ((p & 1) ? W_BUF1 : W_BUF0);
        for (int ks = 0; ks < 8; ++ks) {
            const int kc = ks * 16;
            uint32_t ah[2][4], al[2][4], bh[2][4], bl[2][4];
#pragma unroll
            for (int mt = 0; mt < 2; ++mt) {
                int row = m_base + mt * 16 + (lane & 15);
                int kk = kc + ((lane >> 4) << 3);
                uint32_t off = sw_off(row, kk);
                ldsm4(ah[mt][0], ah[mt][1], ah[mt][2], ah[mt][3], sb + A_HI + off);
                ldsm4(al[mt][0], al[mt][1], al[mt][2], al[mt][3], sb + A_LO + off);
            }
#pragma unroll
            for (int ng = 0; ng < 2; ++ng) {
                int n = n_base + ng * 16 + (lane & 7) + ((lane >> 4) << 3);
                int kk = kc + (((lane >> 3) & 1) << 3);
                uint32_t off = sw_off(n, kk);
                ldsm4(bh[ng][0], bh[ng][1], bh[ng][2], bh[ng][3], wbase + off);
                ldsm4(bl[ng][0], bl[ng][1], bl[ng][2], bl[ng][3], wbase + 32768 + off);
            }
#pragma unroll
            for (int mt = 0; mt < 2; ++mt)
#pragma unroll
                for (int ng = 0; ng < 2; ++ng) {
                    mma16816(acc[mt][ng * 2 + 0], ah[mt][0], ah[mt][1], ah[mt][2], ah[mt][3],
                             bh[ng][0], bh[ng][1]);
                    mma16816(acc[mt][ng * 2 + 1], ah[mt][0], ah[mt][1], ah[mt][2], ah[mt][3],
                             bh[ng][2], bh[ng][3]);
                    mma16816(acc[mt][ng * 2 + 0], ah[mt][0], ah[mt][1], ah[mt][2], ah[mt][3],
                             bl[ng][0], bl[ng][1]);
                    mma16816(acc[mt][ng * 2 + 1], ah[mt][0], ah[mt][1], ah[mt][2], ah[mt][3],
                             bl[ng][2], bl[ng][3]);
                    mma16816(acc[mt][ng * 2 + 0], al[mt][0], al[mt][1], al[mt][2], al[mt][3],
                             bh[ng][0], bh[ng][1]);
                    mma16816(acc[mt][ng * 2 + 1], al[mt][0], al[mt][1], al[mt][2], al[mt][3],
                             bh[ng][2], bh[ng][3]);
                }
        }
        __syncthreads();
    }

    // ---------------- epilogue ----------------
    float bcol[8];
#pragma unroll
    for (int nt = 0; nt < 4; ++nt)
#pragma unroll
        for (int par = 0; par < 2; ++par) {
            int c = n_base + nt * 8 + qc * 2 + par;
            float bb = 0.f;
            if (bias1 != nullptr) bb += bias1[c];
            if (bias2 != nullptr) bb += bias2[c];
            bcol[nt * 2 + par] = bb;
        }

    float cs[8], cq[8];
#pragma unroll
    for (int j = 0; j < 8; ++j) { cs[j] = 0.f; cq[j] = 0.f; }

#pragma unroll
    for (int mt = 0; mt < 2; ++mt)
#pragma unroll
        for (int jh = 0; jh < 2; ++jh) {
            int m = m0 + m_base + mt * 16 + qr + jh * 8;
            bool valid = (m < M);
            float2 vals[4];
#pragma unroll
            for (int nt = 0; nt < 4; ++nt) {
                float v0 = acc[mt][nt][jh * 2 + 0] + bcol[nt * 2 + 0];
                float v1 = acc[mt][nt][jh * 2 + 1] + bcol[nt * 2 + 1];
                if (do_elu) {
                    v0 = (v0 > 0.f) ? v0 : expm1f(v0);
                    v1 = (v1 > 0.f) ? v1 : expm1f(v1);
                }
                v0 *= out_scale; v1 *= out_scale;
                vals[nt] = make_float2(v0, v1);
                if (valid) {
                    cs[nt * 2 + 0] += v0; cq[nt * 2 + 0] += v0 * v0;
                    cs[nt * 2 + 1] += v1; cq[nt * 2 + 1] += v1 * v1;
                }
            }
            if (valid) {
                float* op = Out + (size_t)m * D + n_base + qc * 2;
#pragma unroll
                for (int nt = 0; nt < 4; ++nt)
                    *(float2*)(op + nt * 8) = vals[nt];
            }
        }

    if (bn != nullptr) {
#pragma unroll
        for (int j = 0; j < 8; ++j) {
#pragma unroll
            for (int o = 16; o >= 4; o >>= 1) {
                cs[j] += __shfl_down_sync(0xFFFFFFFFu, cs[j], o);
                cq[j] += __shfl_down_sync(0xFFFFFFFFu, cq[j], o);
            }
        }
        if (lane < 4) {
#pragma unroll
            for (int nt = 0; nt < 4; ++nt)
#pragma unroll
                for (int par = 0; par < 2; ++par) {
                    int c = n_base + nt * 8 + lane * 2 + par;
                    atomicAdd(&bnS[c], cs[nt * 2 + par]);
                    atomicAdd(&bnS[128 + c], cq[nt * 2 + par]);
                }
        }
        __syncthreads();
        if (tid < 256) atomicAdd(&bn[tid], bnS[tid]);
    }
}

// ================= batchnorm =================
__global__ void bn_final(float* __restrict__ bn, const float* __restrict__ g,
                         const float* __restrict__ b, float* __restrict__ scale,
                         float* __restrict__ shift, float invN) {
    int c = threadIdx.x;
    float m = bn[c] * invN;
    float var = bn[D + c] * invN - m * m;
    float rs = rsqrtf(var + 1e-5f);
    float sc = g[c] * rs;
    scale[c] = sc;
    shift[c] = b[c] - m * sc;
    bn[c] = 0.f;
    bn[D + c] = 0.f;
}

__global__ void bn_apply(const float4* __restrict__ x, const float* __restrict__ scale,
                         const float* __restrict__ shift, float4* __restrict__ y, int n4) {
    int i = blockIdx.x * blockDim.x + threadIdx.x;
    if (i >= n4) return;
    int c = (i & 31) * 4;
    float4 v = x[i];
    v.x = v.x * scale[c + 0] + shift[c + 0];
    v.y = v.y * scale[c + 1] + shift[c + 1];
    v.z = v.z * scale[c + 2] + shift[c + 2];
    v.w = v.w * scale[c + 3] + shift[c + 3];
    y[i] = v;
}

// ================= host =================
static inline void launch_gemm(const float* A1, const __nv_bfloat16* W1p,
                               const float* A2, const __nv_bfloat16* W2p,
                               const float* A3, const __nv_bfloat16* W3p,
                               const float* aff_sc, const float* aff_sh, int aff_pass,
                               const float* b1, const float* b2,
                               float out_scale, int do_elu, float* bn,
                               float* Out, int M, cudaStream_t st) {
    gemm_tc<<<(M + 127) / 128, 512, SMEM_TC, st>>>(A1, W1p, A2, W2p, A3, W3p,
                                                   aff_sc, aff_sh, aff_pass, b1, b2,
                                                   out_scale, do_elu, bn, Out, M);
}

static inline void build_csr(const int* src, const int* dst, int E, int N,
                             int* deg, int* bsum, int* rp, int* col, cudaStream_t st) {
    int M = N + 1;
    int nb = (M + 1023) / 1024;
    hist_kernel<<<(E + 255) / 256, 256, 0, st>>>(dst, E, deg);
    scan_sum<<<nb, 256, 0, st>>>(deg, bsum, M);
    scan_offsets<<<1, 32, 0, st>>>(bsum, nb);
    scan_block<<<nb, 256, 0, st>>>(deg, bsum, rp, M);
    fill_kernel<<<(E + 255) / 256, 256, 0, st>>>(src, dst, E, rp, deg, col);
}

extern "C" void kernel_launch(void* const* d_in, const int* in_sizes, int n_in,
                              void* d_out, int out_size) {
    const float* x_student = (const float*)d_in[0];
    const float* x_item    = (const float*)d_in[1];
    const float* Wl_ri = (const float*)d_in[2];
    const float* bl_ri = (const float*)d_in[3];
    const float* Wr_ri = (const float*)d_in[4];
    const float* Wl_rs = (const float*)d_in[5];
    const float* bl_rs = (const float*)d_in[6];
    const float* Wr_rs = (const float*)d_in[7];
    const float* W_p   = (const float*)d_in[8];
    const float* b_p   = (const float*)d_in[9];
    const float* bn_g  = (const float*)d_in[10];
    const float* bn_b  = (const float*)d_in[11];
    const int* resp_src = (const int*)d_in[12];
    const int* resp_dst = (const int*)d_in[13];
    const int* rev_src  = (const int*)d_in[14];
    const int* rev_dst  = (const int*)d_in[15];
    const int* prec_src = (const int*)d_in[16];
    const int* prec_dst = (const int*)d_in[17];
    float* out = (float*)d_out;

    static int configured = 0;
    static cudaStream_t s1, s2, s3;
    static cudaEvent_t evRoot, evPack, evAggS1, evAggP1, evAggS2, evAggP2,
                       evXs1, evXi1, evDone1;
    if (!configured) {
        cudaFuncSetAttribute(gemm_tc, cudaFuncAttributeMaxDynamicSharedMemorySize, SMEM_TC);
        cudaStreamCreateWithFlags(&s1, cudaStreamNonBlocking);
        cudaStreamCreateWithFlags(&s2, cudaStreamNonBlocking);
        cudaStreamCreateWithFlags(&s3, cudaStreamNonBlocking);
        cudaEventCreateWithFlags(&evRoot, cudaEventDisableTiming);
        cudaEventCreateWithFlags(&evPack, cudaEventDisableTiming);
        cudaEventCreateWithFlags(&evAggS1, cudaEventDisableTiming);
        cudaEventCreateWithFlags(&evAggP1, cudaEventDisableTiming);
        cudaEventCreateWithFlags(&evAggS2, cudaEventDisableTiming);
        cudaEventCreateWithFlags(&evAggP2, cudaEventDisableTiming);
        cudaEventCreateWithFlags(&evXs1, cudaEventDisableTiming);
        cudaEventCreateWithFlags(&evXi1, cudaEventDisableTiming);
        cudaEventCreateWithFlags(&evDone1, cudaEventDisableTiming);
        configured = 1;
    }

    float *agg_s, *agg_s2, *agg_p, *agg_i, *xs, *item, *item2, *bn;
    float *sc1, *sh1, *sc2, *sh2;
    __nv_bfloat16* wpack;
    int *deg_a, *deg_b, *deg_c, *bsum_a, *bsum_b, *bsum_c;
    int *rp_resp, *rp_rev, *rp_prec, *col_resp, *col_rev, *col_prec;
    cudaGetSymbolAddress((void**)&agg_s,   g_agg_s);
    cudaGetSymbolAddress((void**)&agg_s2,  g_agg_s2);
    cudaGetSymbolAddress((void**)&agg_p,   g_agg_p);
    cudaGetSymbolAddress((void**)&agg_i,   g_agg_i);
    cudaGetSymbolAddress((void**)&xs,      g_xs);
    cudaGetSymbolAddress((void**)&item,    g_item);
    cudaGetSymbolAddress((void**)&item2,   g_item2);
    cudaGetSymbolAddress((void**)&bn,      g_bn);
    cudaGetSymbolAddress((void**)&sc1,     g_sc1);
    cudaGetSymbolAddress((void**)&sh1,     g_sh1);
    cudaGetSymbolAddress((void**)&sc2,     g_sc2);
    cudaGetSymbolAddress((void**)&sh2,     g_sh2);
    cudaGetSymbolAddress((void**)&wpack,   g_wpack);
    cudaGetSymbolAddress((void**)&deg_a,   g_deg_a);
    cudaGetSymbolAddress((void**)&deg_b,   g_deg_b);
    cudaGetSymbolAddress((void**)&deg_c,   g_deg_c);
    cudaGetSymbolAddress((void**)&bsum_a,  g_bsum_a);
    cudaGetSymbolAddress((void**)&bsum_b,  g_bsum_b);
    cudaGetSymbolAddress((void**)&bsum_c,  g_bsum_c);
    cudaGetSymbolAddress((void**)&rp_resp, g_rp_resp);
    cudaGetSymbolAddress((void**)&rp_rev,  g_rp_rev);
    cudaGetSymbolAddress((void**)&rp_prec, g_rp_prec);
    cudaGetSymbolAddress((void**)&col_resp, g_col_resp);
    cudaGetSymbolAddress((void**)&col_rev,  g_col_rev);
    cudaGetSymbolAddress((void**)&col_prec, g_col_prec);

    const size_t W2off = 5 * 32768;   // layer-2 weight images

    // ---------- fork ----------
    cudaEventRecord(evRoot, 0);
    cudaStreamWaitEvent(s1, evRoot, 0);
    cudaStreamWaitEvent(s2, evRoot, 0);
    cudaStreamWaitEvent(s3, evRoot, 0);

    // stream 0: weight packing; s1/s2/s3: the three CSR builds (private scratch)
    pack_w<<<(10 * 16384 + 255) / 256, 256>>>(Wl_ri, Wr_ri, Wl_rs, Wr_rs, W_p, wpack);
    cudaEventRecord(evPack, 0);
    build_csr(resp_src, resp_dst, E1, NI, deg_a, bsum_a, rp_resp, col_resp, s1);
    build_csr(rev_src,  rev_dst,  E1, NS, deg_b, bsum_b, rp_rev,  col_rev,  s2);
    build_csr(prec_src, prec_dst, E2, NS, deg_c, bsum_c, rp_prec, col_prec, s3);

    cudaStreamWaitEvent(s1, evPack, 0);   // item-GEMM needs weights

    // =================== layer 1 ===================
    // s2: agg_s = mean_rev(x_item)
    agg_csr<<<(NS * 32 + 255) / 256, 256, 0, s2>>>(x_item, rp_rev, col_rev, NS, 0, 0.f,
                                                   nullptr, nullptr, agg_s);
    cudaEventRecord(evAggS1, s2);
    // s3: agg_p = sum_prec(x_student)
    agg_csr<<<(NS * 32 + 255) / 256, 256, 0, s3>>>(x_student, rp_prec, col_prec, NS, 1, 1.f,
                                                   nullptr, nullptr, agg_p);
    cudaEventRecord(evAggP1, s3);

    // s1: item chain: agg_i -> item-GEMM (pre-BN) -> bn_final (sc1/sh1)
    agg_csr<<<(NI * 32 + 255) / 256, 256, 0, s1>>>(x_student, rp_resp, col_resp, NI, 0, 0.f,
                                                   nullptr, nullptr, agg_i);
    launch_gemm(agg_i, wpack + 0 * 32768, x_item, wpack + 1 * 32768, nullptr, nullptr,
                nullptr, nullptr, -1, bl_ri, nullptr, 1.f, 1, bn, item, NI, s1);
    bn_final<<<1, 128, 0, s1>>>(bn, bn_g, bn_b, sc1, sh1, 1.f / (float)NI);
    cudaEventRecord(evXi1, s1);

    // stream 0: stu = 0.5*(agg_s@Wl_rs^T + xs@Wr_rs^T + agg_p@W_p^T + bl_rs + b_p)
    cudaStreamWaitEvent(0, evAggS1, 0);
    cudaStreamWaitEvent(0, evAggP1, 0);
    launch_gemm(agg_s, wpack + 2 * 32768, x_student, wpack + 3 * 32768,
                agg_p, wpack + 4 * 32768, nullptr, nullptr, -1,
                bl_rs, b_p, 0.5f, 0, nullptr, xs, NS, 0);
    cudaEventRecord(evXs1, 0);

    // =================== layer 2 ===================
    float* xi_out = out;                       // items first in output
    float* xs_out = out + (size_t)NI * D;

    // s2: agg_s2 = mean_rev(item) with folded BN (separate buffer: NO wait on evXs1,
    // so this gather overlaps layer-1's stu-GEMM on stream 0)
    cudaStreamWaitEvent(s2, evXi1, 0);
    agg_csr<<<(NS * 32 + 255) / 256, 256, 0, s2>>>(item, rp_rev, col_rev, NS, 2, 0.f,
                                                   sc1, sh1, agg_s2);
    cudaEventRecord(evAggS2, s2);

    // s3: agg_p = sum_prec(xs) (WAR on agg_p cleared by evXs1)
    cudaStreamWaitEvent(s3, evXs1, 0);
    agg_csr<<<(NS * 32 + 255) / 256, 256, 0, s3>>>(xs, rp_prec, col_prec, NS, 1, 1.f,
                                                   nullptr, nullptr, agg_p);
    cudaEventRecord(evAggP2, s3);

    // s1: item chain layer 2: agg_i(xs) -> GEMM (A2 = item with folded BN affine) -> bn -> out
    cudaStreamWaitEvent(s1, evXs1, 0);
    agg_csr<<<(NI * 32 + 255) / 256, 256, 0, s1>>>(xs, rp_resp, col_resp, NI, 0, 0.f,
                                                   nullptr, nullptr, agg_i);
    launch_gemm(agg_i, wpack + W2off + 0 * 32768, item, wpack + W2off + 1 * 32768,
                nullptr, nullptr, sc1, sh1, 1,
                bl_ri + D, nullptr, 1.f, 1, bn, item2, NI, s1);
    bn_final<<<1, 128, 0, s1>>>(bn, bn_g + D, bn_b + D, sc2, sh2, 1.f / (float)NI);
    bn_apply<<<(NI * 32 + 255) / 256, 256, 0, s1>>>((const float4*)item2, sc2, sh2,
                                                    (float4*)xi_out, NI * 32);
    cudaEventRecord(evDone1, s1);

    // stream 0: stu layer 2 -> out students
    cudaStreamWaitEvent(0, evAggS2, 0);
    cudaStreamWaitEvent(0, evAggP2, 0);
    launch_gemm(agg_s2, wpack + W2off + 2 * 32768, xs, wpack + W2off + 3 * 32768,
                agg_p, wpack + W2off + 4 * 32768, nullptr, nullptr, -1,
                bl_rs + D, b_p + D, 0.5f, 0, nullptr, xs_out, NS, 0);

    // ---------- join all branches back to stream 0 ----------
    cudaStreamWaitEvent(0, evDone1, 0);
}